// round 6
// baseline (speedup 1.0000x reference)
#include <cuda_runtime.h>
#include <cuda_fp16.h>
#include <cstdint>

#define BSZ 256
#define MAX_LEN 1024
#define D 256
#define D_ATTN 128

// scratch
__device__ float g_buf[BSZ * D];       // g[b][j]
__device__ __half emb_h[BSZ * D];      // pre-converted emb_q (fp16)

// ---------------------------------------------------------------------------
__device__ __forceinline__ uint32_t smem_u32(const void* p) {
    uint32_t a;
    asm("{ .reg .u64 t; cvta.to.shared.u64 t, %1; cvt.u32.u64 %0, t; }"
        : "=r"(a) : "l"(p));
    return a;
}
__device__ __forceinline__ float tanh_ap(float x) {
    float r;
    asm("tanh.approx.f32 %0, %1;" : "=f"(r) : "f"(x));
    return r;
}
__device__ __forceinline__ void mma_f16(float c[4], const uint32_t a[4],
                                        const uint32_t b[2]) {
    asm volatile(
        "mma.sync.aligned.m16n8k16.row.col.f32.f16.f16.f32 "
        "{%0,%1,%2,%3}, {%4,%5,%6,%7}, {%8,%9}, {%0,%1,%2,%3};\n"
        : "+f"(c[0]), "+f"(c[1]), "+f"(c[2]), "+f"(c[3])
        : "r"(a[0]), "r"(a[1]), "r"(a[2]), "r"(a[3]), "r"(b[0]), "r"(b[1]));
}
#define LDSM4(r0, r1, r2, r3, addr)                                           \
    asm volatile("ldmatrix.sync.aligned.m8n8.x4.shared.b16 {%0,%1,%2,%3}, [%4];" \
                 : "=r"(r0), "=r"(r1), "=r"(r2), "=r"(r3) : "r"(addr))
#define CP16(dst, src)                                                        \
    asm volatile("cp.async.cg.shared.global [%0], [%1], 16;" ::"r"(dst),      \
                 "l"(src) : "memory")
#define CP_COMMIT() asm volatile("cp.async.commit_group;" ::: "memory")
#define CP_WAIT(n) asm volatile("cp.async.wait_group %0;" ::"n"(n) : "memory")

__device__ __forceinline__ uint32_t pack_h2(float x, float y) {
    const __half2 h = __floats2half2_rn(x, y);
    return *(const uint32_t*)&h;
}

// ---------------------------------------------------------------------------
// Kernel 0: emb_q fp32 -> fp16.  32768 threads, float2/thread (latency-bound;
// spread over 128 SMs instead of 64).
// ---------------------------------------------------------------------------
__global__ void k0_cvt(const float* __restrict__ emb_q) {
    const int i = blockIdx.x * blockDim.x + threadIdx.x;  // 32768 float2
    const float2 v = ((const float2*)emb_q)[i];
    ((uint32_t*)emb_h)[i] = pack_h2(v.x, v.y);
}

// ---------------------------------------------------------------------------
// Kernel 1: grid (2, 256): CTA = (b-half n0, j).
// D[m=a(128), n=b(128)] = w_f[j] . emb_q[n0:n0+128]^T, K=256, fp16 mma.
// B (64KB fp16) CTA-resident via 4 cp.async groups; A double-buffered 2x16KB.
// smem 96KB -> 2 CTAs/SM (kills the 1-CTA/SM wave tail of round 5).
// 8 warps: wm = wid>>2 (m 64-range), wn = wid&3 (n 32-range).
// ---------------------------------------------------------------------------
#define A_STG 16384
#define B_BASE 32768
#define B_TILE 16384           // 128 rows x 128B per k-tile
#define K1_DSMEM (B_BASE + 4 * B_TILE + 1024)

__global__ void __launch_bounds__(256, 2) k1_mma(
    const float* __restrict__ w_f,     // [D, D_ATTN, D]
    const float* __restrict__ b_f,     // [D, D_ATTN]
    const float* __restrict__ w_h)     // [D_ATTN]
{
    extern __shared__ char dyn[];
    __shared__ float bias_s[D_ATTN], wh_s[D_ATTN];
    __shared__ float red[2][128];

    const int n0   = blockIdx.x * 128;   // b-range base
    const int j    = blockIdx.y;
    const int tid  = threadIdx.x;
    const int lane = tid & 31;
    const int wid  = tid >> 5;
    const int wm   = wid >> 2;     // 0..1
    const int wn   = wid & 3;      // 0..3
    const int gid  = lane >> 2;
    const int tid4 = lane & 3;

    const uint32_t raw = smem_u32(dyn);
    const uint32_t dbase = (raw + 1023u) & ~1023u;

    if (tid < D_ATTN) {
        bias_s[tid] = b_f[j * D_ATTN + tid];
        wh_s[tid]   = w_h[tid];
    }

    const int c  = tid & 7;       // 16B chunk within 128B row
    const int rb = tid >> 3;      // row base (0..31)

    // ---- B: 4 k-tiles of this CTA's 128 b-rows, via cp.async (4 groups)
#pragma unroll
    for (int kt = 0; kt < 4; kt++) {
#pragma unroll
        for (int i = 0; i < 4; i++) {
            const int r = rb + 32 * i;  // 0..127
            const uint32_t dst = dbase + B_BASE + kt * B_TILE +
                                 r * 128 + ((c ^ (r & 7)) << 4);
            const char* src = (const char*)emb_h +
                              ((size_t)(n0 + r) * 256 + kt * 64 + c * 8) * 2;
            CP16(dst, src);
        }
        CP_COMMIT();
    }

    // ---- A tile 0: load + convert + STS
    const float* Aj = w_f + (size_t)j * D_ATTN * D;
    float4 ra[4][2];
#pragma unroll
    for (int i = 0; i < 4; i++) {
        const int r = rb + 32 * i;  // 0..127
        const float* p = Aj + (size_t)r * 256 + c * 8;
        ra[i][0] = *(const float4*)p;
        ra[i][1] = *(const float4*)(p + 4);
    }
#pragma unroll
    for (int i = 0; i < 4; i++) {
        const int r = rb + 32 * i;
        *(uint4*)(dyn + (dbase - raw) + r * 128 + ((c ^ (r & 7)) << 4)) =
            make_uint4(pack_h2(ra[i][0].x, ra[i][0].y),
                       pack_h2(ra[i][0].z, ra[i][0].w),
                       pack_h2(ra[i][1].x, ra[i][1].y),
                       pack_h2(ra[i][1].z, ra[i][1].w));
    }
    CP_WAIT(3);
    __syncthreads();

    // ---- ldmatrix per-thread bases
    const int lrow = lane & 7;
    const int half = (lane >> 3) & 1;
    const int hi   = lane >> 4;
    uint32_t roffA[4], swzA[4], roffB[2], swzB[2];
#pragma unroll
    for (int m = 0; m < 4; m++) {
        const int r = wm * 64 + m * 16 + half * 8 + lrow;
        roffA[m] = (uint32_t)r * 128;
        swzA[m]  = (uint32_t)(r & 7);
    }
#pragma unroll
    for (int p = 0; p < 2; p++) {
        const int r = wn * 32 + p * 16 + half * 8 + lrow;
        roffB[p] = (uint32_t)r * 128;
        swzB[p]  = (uint32_t)(r & 7);
    }

    float acc[4][4][4];
#pragma unroll
    for (int m = 0; m < 4; m++)
#pragma unroll
        for (int n = 0; n < 4; n++)
#pragma unroll
            for (int q = 0; q < 4; q++) acc[m][n][q] = 0.0f;

    // ---- main loop: 4 k-tiles
#pragma unroll
    for (int t = 0; t < 4; t++) {
        if (t < 3) {
#pragma unroll
            for (int i = 0; i < 4; i++) {
                const int r = rb + 32 * i;
                const float* p = Aj + (size_t)r * 256 + (t + 1) * 64 + c * 8;
                ra[i][0] = *(const float4*)p;
                ra[i][1] = *(const float4*)(p + 4);
            }
        }

        const uint32_t aB = dbase + (uint32_t)(t & 1) * A_STG;
        const uint32_t bB = dbase + B_BASE + (uint32_t)t * B_TILE;
#pragma unroll
        for (int ks = 0; ks < 4; ks++) {
            const uint32_t ch = (uint32_t)(ks * 2 + hi);
            uint32_t af[4][4], bf[4][2];
#pragma unroll
            for (int m = 0; m < 4; m++)
                LDSM4(af[m][0], af[m][1], af[m][2], af[m][3],
                      aB + roffA[m] + ((ch ^ swzA[m]) << 4));
#pragma unroll
            for (int p = 0; p < 2; p++) {
                uint32_t r0, r1, r2, r3;
                LDSM4(r0, r1, r2, r3, bB + roffB[p] + ((ch ^ swzB[p]) << 4));
                bf[2 * p][0] = r0; bf[2 * p + 1][0] = r1;
                bf[2 * p][1] = r2; bf[2 * p + 1][1] = r3;
            }
#pragma unroll
            for (int m = 0; m < 4; m++)
#pragma unroll
                for (int n = 0; n < 4; n++) mma_f16(acc[m][n], af[m], bf[n]);
        }

        if (t < 3) {
            __syncthreads();
            char* dp = dyn + (dbase - raw) + ((t + 1) & 1) * A_STG;
#pragma unroll
            for (int i = 0; i < 4; i++) {
                const int r = rb + 32 * i;
                *(uint4*)(dp + r * 128 + ((c ^ (r & 7)) << 4)) =
                    make_uint4(pack_h2(ra[i][0].x, ra[i][0].y),
                               pack_h2(ra[i][0].z, ra[i][0].w),
                               pack_h2(ra[i][1].x, ra[i][1].y),
                               pack_h2(ra[i][1].z, ra[i][1].w));
            }
            if (t == 0) CP_WAIT(2);
            else if (t == 1) CP_WAIT(1);
            else CP_WAIT(0);
            __syncthreads();
        }
    }

    // ---- epilogue: g[b][j] = sum_a tanh(D[a,b] + bias[a]) * wh[a]
    float biasv[4][2], whv[4][2];
#pragma unroll
    for (int m = 0; m < 4; m++)
#pragma unroll
        for (int h = 0; h < 2; h++) {
            const int a = wm * 64 + m * 16 + h * 8 + gid;
            biasv[m][h] = bias_s[a];
            whv[m][h]   = wh_s[a];
        }

#pragma unroll
    for (int n = 0; n < 4; n++) {
        float p0 = 0.0f, p1 = 0.0f;
#pragma unroll
        for (int m = 0; m < 4; m++) {
            p0 += tanh_ap(acc[m][n][0] + biasv[m][0]) * whv[m][0]
                + tanh_ap(acc[m][n][2] + biasv[m][1]) * whv[m][1];
            p1 += tanh_ap(acc[m][n][1] + biasv[m][0]) * whv[m][0]
                + tanh_ap(acc[m][n][3] + biasv[m][1]) * whv[m][1];
        }
#pragma unroll
        for (int o = 4; o <= 16; o <<= 1) {
            p0 += __shfl_xor_sync(0xffffffffu, p0, o);
            p1 += __shfl_xor_sync(0xffffffffu, p1, o);
        }
        if (gid == 0) {
            const int col = wn * 32 + n * 8 + tid4 * 2;
            red[wm][col]     = p0;
            red[wm][col + 1] = p1;
        }
    }
    __syncthreads();
    if (tid < 128)
        g_buf[(size_t)(n0 + tid) * D + j] = red[0][tid] + red[1][tid];
}

// ---------------------------------------------------------------------------
// Kernel 2: out[b,l] = sum_j emb_iseq[b,l,j] * g[b,j]   (unchanged)
// ---------------------------------------------------------------------------
__global__ void __launch_bounds__(256) k2_weight(
    const float* __restrict__ emb_iseq,  // [BSZ, MAX_LEN, D]
    float* __restrict__ out)             // [BSZ, MAX_LEN]
{
    const int b   = blockIdx.y;
    const int l0  = blockIdx.x * 64;
    const int tid = threadIdx.x;

    __shared__ float gs[D];
    gs[tid] = g_buf[(size_t)b * D + tid];
    __syncthreads();

    const int warp = tid >> 5;
    const int lane = tid & 31;
    const int l = l0 + warp * 8;

    const float4* base = (const float4*)(emb_iseq + ((size_t)b * MAX_LEN + l) * D);

    float4 e[8][2];
#pragma unroll
    for (int r = 0; r < 8; r++)
#pragma unroll
        for (int i = 0; i < 2; i++)
            e[r][i] = __ldcs(&base[r * 64 + i * 32 + lane]);

    const float4* gv = (const float4*)gs;
    const float4 g0 = gv[lane];
    const float4 g1 = gv[lane + 32];

    float acc[8];
#pragma unroll
    for (int r = 0; r < 8; r++) {
        acc[r] = e[r][0].x * g0.x + e[r][0].y * g0.y + e[r][0].z * g0.z + e[r][0].w * g0.w
               + e[r][1].x * g1.x + e[r][1].y * g1.y + e[r][1].z * g1.z + e[r][1].w * g1.w;
    }
#pragma unroll
    for (int r = 0; r < 8; r++)
#pragma unroll
        for (int o = 16; o; o >>= 1)
            acc[r] += __shfl_xor_sync(0xffffffffu, acc[r], o);

    if (lane == 0) {
#pragma unroll
        for (int r = 0; r < 8; r++)
            out[(size_t)b * MAX_LEN + l + r] = acc[r];
    }
}

// ---------------------------------------------------------------------------

extern "C" void kernel_launch(void* const* d_in, const int* in_sizes, int n_in,
                              void* d_out, int out_size)
{
    const float* emb_q    = (const float*)d_in[0];
    const float* emb_iseq = (const float*)d_in[1];
    const float* w_f      = (const float*)d_in[2];
    const float* b_f      = (const float*)d_in[3];
    const float* w_h      = (const float*)d_in[4];
    float* out = (float*)d_out;

    cudaFuncSetAttribute(k1_mma, cudaFuncAttributeMaxDynamicSharedMemorySize,
                         K1_DSMEM);

    k0_cvt<<<128, 256>>>(emb_q);

    dim3 g1(2, D);  // (b-half, j)
    k1_mma<<<g1, 256, K1_DSMEM>>>(w_f, b_f, w_h);

    dim3 g2(MAX_LEN / 64, BSZ);
    k2_weight<<<g2, 256>>>(emb_iseq, out);
}